// round 8
// baseline (speedup 1.0000x reference)
#include <cuda_runtime.h>
#include <cuda_bf16.h>
#include <cstdint>

// ===========================================================================
// CrossModalAttention collapses analytically:
//   fa[b,s,:] constant over s => K_a, V_a constant over t
//   => softmax uniform => attn_out[b,s,:] == va[b,:]
//   => out = text @ Wt + bt + va[b]      (one real GEMM)
// GEMM on tensor cores via bf16x3 fp32 emulation (Ah*Bh + Ah*Bl + Al*Bh).
// Round 8: single merged prep kernel (split + wsplit + va in one launch),
// evict-first (.cs) output stores to keep A hi/lo L2-resident, epilogue
// bias+va prefetched before the mainloop. Mainloop = round-4 best config
// (CTA 256x128, 512 thr, KT=64, 2-stage).
// ===========================================================================

#define BATCH 8
#define SEQ   2048
#define DM    768
#define DAUD  16
#define M_TOT (BATCH * SEQ)

__device__ float g_va[BATCH * DM];
__device__ __nv_bfloat16 g_Ah[M_TOT * DM];
__device__ __nv_bfloat16 g_Al[M_TOT * DM];
__device__ __nv_bfloat16 g_Bh[DM * DM];     // Wt transposed: [N, K]
__device__ __nv_bfloat16 g_Bl[DM * DM];

// ------------------------------ helpers ------------------------------------
__device__ __forceinline__ uint32_t smem_u32(const void* p) {
    uint32_t r;
    asm("{ .reg .u64 t; cvta.to.shared.u64 t, %1; cvt.u32.u64 %0, t; }"
        : "=r"(r) : "l"(p));
    return r;
}

#define SWZ(o) ((o) ^ (((o) >> 3) & 0x70))

__device__ __forceinline__ void cpasync16(uint32_t dst, const void* src) {
    asm volatile("cp.async.cg.shared.global [%0], [%1], 16;"
                 :: "r"(dst), "l"(src));
}

__device__ __forceinline__ void ldsm4(uint32_t* r, uint32_t addr) {
    asm volatile("ldmatrix.sync.aligned.m8n8.x4.shared.b16 {%0,%1,%2,%3}, [%4];"
                 : "=r"(r[0]), "=r"(r[1]), "=r"(r[2]), "=r"(r[3])
                 : "r"(addr));
}

__device__ __forceinline__ void mma16816(float* d,
                                         const uint32_t* a,
                                         uint32_t b0, uint32_t b1) {
    asm volatile(
        "mma.sync.aligned.m16n8k16.row.col.f32.bf16.bf16.f32 "
        "{%0,%1,%2,%3}, {%4,%5,%6,%7}, {%8,%9}, {%0,%1,%2,%3};"
        : "+f"(d[0]), "+f"(d[1]), "+f"(d[2]), "+f"(d[3])
        : "r"(a[0]), "r"(a[1]), "r"(a[2]), "r"(a[3]), "r"(b0), "r"(b1));
}

// Streaming (evict-first) 8-byte store: output is write-once, keep A in L2.
__device__ __forceinline__ void stg_cs_v2(float* p, float x, float y) {
    asm volatile("st.global.cs.v2.f32 [%0], {%1, %2};"
                 :: "l"(p), "f"(x), "f"(y) : "memory");
}

// ---------------------------------------------------------------------------
// Merged prep kernel (256 threads/block):
//   blocks [0, NB_SPLIT)                 : text fp32 -> bf16 hi/lo
//   blocks [NB_SPLIT, NB_SPLIT+NB_W)     : Wt transpose + split
//   blocks [NB_SPLIT+NB_W, +BATCH)       : va = (ac@Wa+ba)@Wv + bv
// ---------------------------------------------------------------------------
#define NB_SPLIT ((M_TOT * DM) / 8 / 256)          // 6144
#define NB_W     ((DM / 32) * (DM / 32))           // 576
#define NB_TOTAL (NB_SPLIT + NB_W + BATCH)

__global__ void prep_kernel(const float* __restrict__ text,
                            const float* __restrict__ W,
                            const float* __restrict__ ac,
                            const float* __restrict__ Wa,
                            const float* __restrict__ ba,
                            const float* __restrict__ Wv,
                            const float* __restrict__ bv) {
    const int blk = blockIdx.x;

    if (blk < NB_SPLIT) {
        // ---- text split: 8 elems/thread, 16B stores ----
        size_t i = ((size_t)blk * 256 + threadIdx.x) * 8;
        float4 v0 = *(const float4*)(text + i);
        float4 v1 = *(const float4*)(text + i + 4);
        float f[8] = {v0.x, v0.y, v0.z, v0.w, v1.x, v1.y, v1.z, v1.w};
        __nv_bfloat162 h[4], l[4];
#pragma unroll
        for (int j = 0; j < 4; j++) {
            __nv_bfloat16 h0 = __float2bfloat16(f[2*j]);
            __nv_bfloat16 h1 = __float2bfloat16(f[2*j+1]);
            __nv_bfloat16 l0 = __float2bfloat16(f[2*j]   - __bfloat162float(h0));
            __nv_bfloat16 l1 = __float2bfloat16(f[2*j+1] - __bfloat162float(h1));
            h[j] = __halves2bfloat162(h0, h1);
            l[j] = __halves2bfloat162(l0, l1);
        }
        *(uint4*)(g_Ah + i) = *(const uint4*)h;
        *(uint4*)(g_Al + i) = *(const uint4*)l;
        return;
    }

    if (blk < NB_SPLIT + NB_W) {
        // ---- Wt transpose + split: 32x32 tile, 256 threads (32x8) ----
        __shared__ float tile[32][33];
        const int w = blk - NB_SPLIT;
        const int n0 = (w % (DM / 32)) * 32, k0 = (w / (DM / 32)) * 32;
        const int tx = threadIdx.x & 31, ty = threadIdx.x >> 5;
        for (int r = ty; r < 32; r += 8)
            tile[r][tx] = W[(size_t)(k0 + r) * DM + n0 + tx];
        __syncthreads();
        for (int r = ty; r < 32; r += 8) {
            float v = tile[tx][r];                 // = W[k0+tx][n0+r]
            __nv_bfloat16 h = __float2bfloat16(v);
            __nv_bfloat16 lo = __float2bfloat16(v - __bfloat162float(h));
            g_Bh[(size_t)(n0 + r) * DM + k0 + tx] = h;
            g_Bl[(size_t)(n0 + r) * DM + k0 + tx] = lo;
        }
        return;
    }

    // ---- va: 256 threads, 3 output columns each ----
    {
        __shared__ float fa[DM];
        __shared__ float acs[DAUD];
        const int b = blk - NB_SPLIT - NB_W;
        const int t = threadIdx.x;
        if (t < DAUD) acs[t] = ac[b * DAUD + t];
        __syncthreads();
#pragma unroll
        for (int r = 0; r < 3; r++) {
            const int col = t + r * 256;
            float v = ba[col];
#pragma unroll
            for (int k = 0; k < DAUD; k++) v += acs[k] * Wa[k * DM + col];
            fa[col] = v;
        }
        __syncthreads();
#pragma unroll
        for (int r = 0; r < 3; r++) {
            const int col = t + r * 256;
            float o = bv[col];
            for (int e = 0; e < DM; e++) o += fa[e] * Wv[e * DM + col];
            g_va[b * DM + col] = o;
        }
    }
}

// ---------------------------------------------------------------------------
// GEMM: CTA tile 256x128, 512 threads (16 warps, 4x4), warp tile 64x32.
// KT=64 chunks, 2-stage cp.async ring, SW128 smem.
// ---------------------------------------------------------------------------
#define BM      256
#define BN      128
#define KT      64
#define KSTEPS  4
#define NCHUNK  (DM / KT)                 // 12
#define TILE_A  (BM * 128)                // 32 KB (256 rows x 128B)
#define TILE_B  (BN * 128)                // 16 KB
#define STAGEB  (2 * TILE_A + 2 * TILE_B) // 96 KB
#define SMEM_DYN (2 * STAGEB + 1024)

__device__ __forceinline__ void load_chunk(uint32_t stg,
                                           const __nv_bfloat16* const* g0,
                                           int k0, int tid) {
    // A tiles: 2048 x 16B each, 4 iters/thread
#pragma unroll
    for (int t = 0; t < 2; t++) {
        const uint32_t tb = stg + t * TILE_A;
#pragma unroll
        for (int j = 0; j < 4; j++) {
            const int q = tid + j * 512;          // 0..2047
            const int row = q >> 3, cc = q & 7;
            cpasync16(tb + SWZ(row * 128 + cc * 16),
                      g0[t] + (size_t)row * DM + k0 + cc * 8);
        }
    }
    // B tiles: 1024 x 16B each, 2 iters/thread
#pragma unroll
    for (int t = 0; t < 2; t++) {
        const uint32_t tb = stg + 2 * TILE_A + t * TILE_B;
#pragma unroll
        for (int j = 0; j < 2; j++) {
            const int q = tid + j * 512;          // 0..1023
            const int row = q >> 3, cc = q & 7;
            cpasync16(tb + SWZ(row * 128 + cc * 16),
                      g0[2 + t] + (size_t)row * DM + k0 + cc * 8);
        }
    }
    asm volatile("cp.async.commit_group;");
}

__global__ __launch_bounds__(512, 1)
void gemm_kernel(const float* __restrict__ bias, float* __restrict__ out) {
    extern __shared__ char dynsmem[];
    uint32_t base = smem_u32(dynsmem);
    base = (base + 1023u) & ~1023u;

    const int tid = threadIdx.x;
    const int wid = tid >> 5, lane = tid & 31;
    const int wm = wid >> 2, wn = wid & 3;   // 4x4 warp grid
    const int bn = blockIdx.x, bm = blockIdx.y;

    const __nv_bfloat16* g0[4] = {
        g_Ah + (size_t)bm * BM * DM,
        g_Al + (size_t)bm * BM * DM,
        g_Bh + (size_t)bn * BN * DM,
        g_Bl + (size_t)bn * BN * DM };

    float acc[4][4][4] = {};

    load_chunk(base + 0 * STAGEB, g0, 0 * KT, tid);
    load_chunk(base + 1 * STAGEB, g0, 1 * KT, tid);

    // Prefetch epilogue addends: bias[col] + va[b][col] for this thread's
    // 4 n-tiles (x2 columns). L2-hot; hides epilogue latency behind mainloop.
    const int bidx = bm >> 3;                // (bm*256)/2048
    float addv[4][2];
#pragma unroll
    for (int nt = 0; nt < 4; nt++) {
        const int col = bn * BN + wn * 32 + nt * 8 + (lane & 3) * 2;
        addv[nt][0] = bias[col]     + g_va[bidx * DM + col];
        addv[nt][1] = bias[col + 1] + g_va[bidx * DM + col + 1];
    }

    for (int c = 0; c < NCHUNK; ++c) {
        asm volatile("cp.async.wait_group 1;");
        __syncthreads();

        const uint32_t stg = base + (c & 1) * STAGEB;
        const uint32_t Ah = stg,                 Al = stg + TILE_A;
        const uint32_t Bh = stg + 2 * TILE_A,    Bl = Bh + TILE_B;

#pragma unroll
        for (int ks = 0; ks < KSTEPS; ks++) {
            uint32_t ah[4][4], al[4][4];
            const int akb = ks * 32 + (lane >> 4) * 16;
#pragma unroll
            for (int mt = 0; mt < 4; mt++) {
                const int row = wm * 64 + mt * 16 + (lane & 15);
                const uint32_t off = SWZ(row * 128 + akb);
                ldsm4(ah[mt], Ah + off);
                ldsm4(al[mt], Al + off);
            }
            const int brow_base = wn * 32 + (lane & 7) + ((lane >> 4) << 3);
            const int bkb = ks * 32 + ((lane >> 3) & 1) * 16;
#pragma unroll
            for (int p = 0; p < 2; p++) {
                uint32_t bh[4], bl[4];
                const uint32_t off = SWZ((brow_base + p * 16) * 128 + bkb);
                ldsm4(bh, Bh + off);
                ldsm4(bl, Bl + off);
#pragma unroll
                for (int mt = 0; mt < 4; mt++) {
                    float* d0 = acc[mt][2 * p];
                    float* d1 = acc[mt][2 * p + 1];
                    mma16816(d0, ah[mt], bh[0], bh[1]);
                    mma16816(d1, ah[mt], bh[2], bh[3]);
                    mma16816(d0, ah[mt], bl[0], bl[1]);
                    mma16816(d1, ah[mt], bl[2], bl[3]);
                    mma16816(d0, al[mt], bh[0], bh[1]);
                    mma16816(d1, al[mt], bh[2], bh[3]);
                }
            }
        }
        __syncthreads();
        if (c + 2 < NCHUNK)
            load_chunk(stg, g0, (c + 2) * KT, tid);
        else
            asm volatile("cp.async.commit_group;");   // keep group count in step
    }

    // Epilogue: out = acc + (bias + va) [prefetched], streaming stores.
#pragma unroll
    for (int mt = 0; mt < 4; mt++) {
        const int r0 = bm * BM + wm * 64 + mt * 16 + (lane >> 2);
#pragma unroll
        for (int nt = 0; nt < 4; nt++) {
            const int col = bn * BN + wn * 32 + nt * 8 + (lane & 3) * 2;
            stg_cs_v2(out + (size_t)r0 * DM + col,
                      acc[mt][nt][0] + addv[nt][0],
                      acc[mt][nt][1] + addv[nt][1]);
            stg_cs_v2(out + (size_t)(r0 + 8) * DM + col,
                      acc[mt][nt][2] + addv[nt][0],
                      acc[mt][nt][3] + addv[nt][1]);
        }
    }
}

// ---------------------------------------------------------------------------
// Launch. Input order: text, acoustic, Wt, bt, Wa, ba, Wq,bq, Wk,bk, Wv,bv
// ---------------------------------------------------------------------------
extern "C" void kernel_launch(void* const* d_in, const int* in_sizes, int n_in,
                              void* d_out, int out_size) {
    const float* text = (const float*)d_in[0];
    const float* ac   = (const float*)d_in[1];
    const float* Wt   = (const float*)d_in[2];
    const float* bt   = (const float*)d_in[3];
    const float* Wa   = (const float*)d_in[4];
    const float* ba   = (const float*)d_in[5];
    const float* Wv   = (const float*)d_in[10];
    const float* bv   = (const float*)d_in[11];
    float* out = (float*)d_out;

    cudaFuncSetAttribute(gemm_kernel,
                         cudaFuncAttributeMaxDynamicSharedMemorySize, SMEM_DYN);

    prep_kernel<<<NB_TOTAL, 256>>>(text, Wt, ac, Wa, ba, Wv, bv);
    gemm_kernel<<<dim3(DM / BN, M_TOT / BM), 512, SMEM_DYN>>>(bt, out);
}

// round 11
// speedup vs baseline: 1.2619x; 1.2619x over previous
#include <cuda_runtime.h>
#include <cuda_bf16.h>
#include <cstdint>

// ===========================================================================
// CrossModalAttention collapses analytically:
//   fa[b,s,:] constant over s => K_a, V_a constant over t
//   => softmax uniform => attn_out[b,s,:] == va[b,:]
//   => out = text @ Wt + bt + va[b]      (one real GEMM)
// GEMM on tensor cores via bf16x3 fp32 emulation (Ah*Bh + Ah*Bl + Al*Bh).
// Round 10: fix round-9 deadlock. Default cp.async.mbarrier.arrive is
// self-balancing (inc-then-arrive) so the full barrier never flipped.
// Replaced with commit_group / wait_group 1 + explicit mbarrier.arrive from
// the producer warps. Same 128x96 tiles (2048 CTAs, 1.2% wave tail),
// 2 producer + 6 consumer warps, 2 CTAs/SM, no mainloop __syncthreads.
// ===========================================================================

#define BATCH 8
#define SEQ   2048
#define DM    768
#define DAUD  16
#define M_TOT (BATCH * SEQ)

__device__ float g_va[BATCH * DM];
__device__ __nv_bfloat16 g_Ah[M_TOT * DM];
__device__ __nv_bfloat16 g_Al[M_TOT * DM];
__device__ __nv_bfloat16 g_Bh[DM * DM];     // Wt transposed: [N, K]
__device__ __nv_bfloat16 g_Bl[DM * DM];

// ------------------------------ helpers ------------------------------------
__device__ __forceinline__ uint32_t smem_u32(const void* p) {
    uint32_t r;
    asm("{ .reg .u64 t; cvta.to.shared.u64 t, %1; cvt.u32.u64 %0, t; }"
        : "=r"(r) : "l"(p));
    return r;
}

#define SWZ(o) ((o) ^ (((o) >> 3) & 0x70))

__device__ __forceinline__ void cpasync16(uint32_t dst, const void* src) {
    asm volatile("cp.async.cg.shared.global [%0], [%1], 16;"
                 :: "r"(dst), "l"(src));
}

__device__ __forceinline__ void ldsm4(uint32_t* r, uint32_t addr) {
    asm volatile("ldmatrix.sync.aligned.m8n8.x4.shared.b16 {%0,%1,%2,%3}, [%4];"
                 : "=r"(r[0]), "=r"(r[1]), "=r"(r[2]), "=r"(r[3])
                 : "r"(addr));
}

__device__ __forceinline__ void mma16816(float* d,
                                         const uint32_t* a,
                                         uint32_t b0, uint32_t b1) {
    asm volatile(
        "mma.sync.aligned.m16n8k16.row.col.f32.bf16.bf16.f32 "
        "{%0,%1,%2,%3}, {%4,%5,%6,%7}, {%8,%9}, {%0,%1,%2,%3};"
        : "+f"(d[0]), "+f"(d[1]), "+f"(d[2]), "+f"(d[3])
        : "r"(a[0]), "r"(a[1]), "r"(a[2]), "r"(a[3]), "r"(b0), "r"(b1));
}

__device__ __forceinline__ void stg_cs_v2(float* p, float x, float y) {
    asm volatile("st.global.cs.v2.f32 [%0], {%1, %2};"
                 :: "l"(p), "f"(x), "f"(y) : "memory");
}

#define MBARRIER_INIT(addr, cnt) \
    asm volatile("mbarrier.init.shared.b64 [%0], %1;" \
                 :: "r"((uint32_t)(addr)), "r"((uint32_t)(cnt)) : "memory")

#define MBARRIER_ARRIVE(addr) \
    asm volatile("mbarrier.arrive.shared.b64 _, [%0];" \
                 :: "r"((uint32_t)(addr)) : "memory")

#define MBARRIER_WAIT_PARITY(addr, parity) do {                               \
    uint32_t _m = (uint32_t)(addr);                                           \
    uint32_t _p = (uint32_t)(parity);                                         \
    uint32_t _done;                                                           \
    asm volatile(                                                             \
        "{\n\t.reg .pred p;\n\t"                                              \
        "mbarrier.try_wait.parity.acquire.cta.shared::cta.b64 p, [%1], %2;\n\t" \
        "selp.b32 %0, 1, 0, p;\n\t}"                                          \
        : "=r"(_done) : "r"(_m), "r"(_p) : "memory");                         \
    if (!_done) {                                                             \
        asm volatile(                                                         \
            "{\n\t.reg .pred P1;\n\t"                                         \
            "WAIT_LOOP_%=:\n\t"                                               \
            "mbarrier.try_wait.parity.acquire.cta.shared::cta.b64 P1, [%0], %1, 0x989680;\n\t" \
            "@P1 bra.uni WAIT_DONE_%=;\n\t"                                   \
            "bra.uni WAIT_LOOP_%=;\n\t"                                       \
            "WAIT_DONE_%=:\n\t}"                                              \
            :: "r"(_m), "r"(_p) : "memory");                                  \
    }                                                                         \
} while (0)

// ---------------------------------------------------------------------------
// Prep A: fp32 text -> (bf16 hi, bf16 lo), 8 elems/thread, 16B stores.
// ---------------------------------------------------------------------------
__global__ void split_text_kernel(const float* __restrict__ x) {
    size_t i = ((size_t)blockIdx.x * blockDim.x + threadIdx.x) * 8;
    float4 v0 = *(const float4*)(x + i);
    float4 v1 = *(const float4*)(x + i + 4);
    float f[8] = {v0.x, v0.y, v0.z, v0.w, v1.x, v1.y, v1.z, v1.w};
    __nv_bfloat162 h[4], l[4];
#pragma unroll
    for (int j = 0; j < 4; j++) {
        __nv_bfloat16 h0 = __float2bfloat16(f[2*j]);
        __nv_bfloat16 h1 = __float2bfloat16(f[2*j+1]);
        __nv_bfloat16 l0 = __float2bfloat16(f[2*j]   - __bfloat162float(h0));
        __nv_bfloat16 l1 = __float2bfloat16(f[2*j+1] - __bfloat162float(h1));
        h[j] = __halves2bfloat162(h0, h1);
        l[j] = __halves2bfloat162(l0, l1);
    }
    *(uint4*)(g_Ah + i) = *(const uint4*)h;
    *(uint4*)(g_Al + i) = *(const uint4*)l;
}

// ---------------------------------------------------------------------------
// Prep B: transpose + split Wt[K,N] -> g_Bh/g_Bl [N,K]
// ---------------------------------------------------------------------------
__global__ void wsplit_kernel(const float* __restrict__ W) {
    __shared__ float tile[32][33];
    int n0 = blockIdx.x * 32, k0 = blockIdx.y * 32;
    int tx = threadIdx.x, ty = threadIdx.y;
    for (int r = ty; r < 32; r += 8)
        tile[r][tx] = W[(size_t)(k0 + r) * DM + n0 + tx];
    __syncthreads();
    for (int r = ty; r < 32; r += 8) {
        float v = tile[tx][r];                 // = W[k0+tx][n0+r]
        __nv_bfloat16 h = __float2bfloat16(v);
        __nv_bfloat16 l = __float2bfloat16(v - __bfloat162float(h));
        g_Bh[(size_t)(n0 + r) * DM + k0 + tx] = h;
        g_Bl[(size_t)(n0 + r) * DM + k0 + tx] = l;
    }
}

// ---------------------------------------------------------------------------
// Prep C: va[b,:] = (acoustic[b,:] @ Wa + ba) @ Wv + bv
// ---------------------------------------------------------------------------
__global__ void va_kernel(const float* __restrict__ ac,
                          const float* __restrict__ Wa,
                          const float* __restrict__ ba,
                          const float* __restrict__ Wv,
                          const float* __restrict__ bv) {
    __shared__ float fa[DM];
    __shared__ float acs[DAUD];
    const int b = blockIdx.x;
    const int t = threadIdx.x;
    if (t < DAUD) acs[t] = ac[b * DAUD + t];
    __syncthreads();
    float v = ba[t];
#pragma unroll
    for (int k = 0; k < DAUD; k++) v += acs[k] * Wa[k * DM + t];
    fa[t] = v;
    __syncthreads();
    float o = bv[t];
    for (int e = 0; e < DM; e++) o += fa[e] * Wv[e * DM + t];
    g_va[b * DM + t] = o;
}

// ---------------------------------------------------------------------------
// GEMM: CTA tile 128x96, 256 threads. Warps 0-5 consumers (2x3 grid, warp
// tile 64x32), warps 6-7 producers. KT=64, 2-stage mbarrier pipeline.
// Full-signal path: commit_group / wait_group 1 + explicit mbarrier.arrive.
// ---------------------------------------------------------------------------
#define BM      128
#define BN      96
#define KT      64
#define KSTEPS  4
#define NCHUNK  (DM / KT)                 // 12
#define TILE_A  (BM * 128)                // 16 KB
#define TILE_B  (BN * 128)                // 12 KB
#define STAGEB  (2 * TILE_A + 2 * TILE_B) // 56 KB
#define SMEM_DYN (2 * STAGEB)             // 114688 B

__global__ __launch_bounds__(256, 2)
void gemm_kernel(const float* __restrict__ bias, float* __restrict__ out) {
    extern __shared__ __align__(16) char dynsmem[];
    __shared__ __align__(8) uint64_t s_bar[4];   // full[0],full[1],empty[0],empty[1]

    const uint32_t base = smem_u32(dynsmem);
    const int tid = threadIdx.x;
    const int wid = tid >> 5, lane = tid & 31;
    const int bn = blockIdx.x, bm = blockIdx.y;

    const uint32_t full0  = smem_u32(&s_bar[0]);
    const uint32_t empty0 = smem_u32(&s_bar[2]);

    if (tid == 0) {
        MBARRIER_INIT(full0 + 0,  64);    // 64 producer threads arrive
        MBARRIER_INIT(full0 + 8,  64);
        MBARRIER_INIT(empty0 + 0, 192);   // 192 consumer threads arrive
        MBARRIER_INIT(empty0 + 8, 192);
    }
    __syncthreads();

    const __nv_bfloat16* g0[4] = {
        g_Ah + (size_t)bm * BM * DM,
        g_Al + (size_t)bm * BM * DM,
        g_Bh + (size_t)bn * BN * DM,
        g_Bl + (size_t)bn * BN * DM };

    if (wid >= 6) {
        // ------------------------- producer -------------------------------
        const int ptid = tid - 192;             // 0..63
        for (int c = 0; c < NCHUNK; ++c) {
            const int s = c & 1;
            if (c >= 2)
                MBARRIER_WAIT_PARITY(empty0 + 8 * s, ((c >> 1) + 1) & 1);

            const uint32_t stg = base + s * STAGEB;
            const int k0 = c * KT;
            // A hi/lo: 1024 lines of 16B each
#pragma unroll
            for (int t = 0; t < 2; t++) {
                const uint32_t tb = stg + t * TILE_A;
#pragma unroll
                for (int j = 0; j < 16; j++) {
                    const int q = ptid + j * 64;         // 0..1023
                    const int row = q >> 3, cc = q & 7;
                    cpasync16(tb + SWZ(row * 128 + cc * 16),
                              g0[t] + (size_t)row * DM + k0 + cc * 8);
                }
            }
            // B hi/lo: 768 lines each
#pragma unroll
            for (int t = 0; t < 2; t++) {
                const uint32_t tb = stg + 2 * TILE_A + t * TILE_B;
#pragma unroll
                for (int j = 0; j < 12; j++) {
                    const int q = ptid + j * 64;         // 0..767
                    const int row = q >> 3, cc = q & 7;
                    cpasync16(tb + SWZ(row * 128 + cc * 16),
                              g0[2 + t] + (size_t)row * DM + k0 + cc * 8);
                }
            }
            asm volatile("cp.async.commit_group;");
            if (c >= 1) {
                // Chunk c-1's group is now the only one besides the newest.
                asm volatile("cp.async.wait_group 1;");
                MBARRIER_ARRIVE(full0 + 8 * ((c - 1) & 1));
            }
        }
        asm volatile("cp.async.wait_group 0;");
        MBARRIER_ARRIVE(full0 + 8 * ((NCHUNK - 1) & 1));
        return;
    }

    // --------------------------- consumer ---------------------------------
    const int wm = wid / 3;                 // 0..1
    const int wn = wid - wm * 3;            // 0..2

    // Prefetch epilogue addends (bias + va[b]) while pipeline fills.
    const int bidx = bm >> 4;               // (bm*128)/2048
    float addv[4][2];
#pragma unroll
    for (int nt = 0; nt < 4; nt++) {
        const int col = bn * BN + wn * 32 + nt * 8 + (lane & 3) * 2;
        addv[nt][0] = bias[col]     + g_va[bidx * DM + col];
        addv[nt][1] = bias[col + 1] + g_va[bidx * DM + col + 1];
    }

    float acc[4][4][4] = {};

    for (int c = 0; c < NCHUNK; ++c) {
        const int s = c & 1;
        MBARRIER_WAIT_PARITY(full0 + 8 * s, (c >> 1) & 1);

        const uint32_t stg = base + s * STAGEB;
        const uint32_t Ah = stg,               Al = stg + TILE_A;
        const uint32_t Bh = stg + 2 * TILE_A,  Bl = Bh + TILE_B;

#pragma unroll
        for (int ks = 0; ks < KSTEPS; ks++) {
            uint32_t ah[4][4], al[4][4];
            const int akb = ks * 32 + (lane >> 4) * 16;
#pragma unroll
            for (int mt = 0; mt < 4; mt++) {
                const int row = wm * 64 + mt * 16 + (lane & 15);
                const uint32_t off = SWZ(row * 128 + akb);
                ldsm4(ah[mt], Ah + off);
                ldsm4(al[mt], Al + off);
            }
            const int brow_base = wn * 32 + (lane & 7) + ((lane >> 4) << 3);
            const int bkb = ks * 32 + ((lane >> 3) & 1) * 16;
#pragma unroll
            for (int p = 0; p < 2; p++) {
                uint32_t bh[4], bl[4];
                const uint32_t off = SWZ((brow_base + p * 16) * 128 + bkb);
                ldsm4(bh, Bh + off);
                ldsm4(bl, Bl + off);
#pragma unroll
                for (int mt = 0; mt < 4; mt++) {
                    float* d0 = acc[mt][2 * p];
                    float* d1 = acc[mt][2 * p + 1];
                    mma16816(d0, ah[mt], bh[0], bh[1]);
                    mma16816(d1, ah[mt], bh[2], bh[3]);
                    mma16816(d0, ah[mt], bl[0], bl[1]);
                    mma16816(d1, ah[mt], bl[2], bl[3]);
                    mma16816(d0, al[mt], bh[0], bh[1]);
                    mma16816(d1, al[mt], bh[2], bh[3]);
                }
            }
        }
        MBARRIER_ARRIVE(empty0 + 8 * s);
    }

    // Epilogue: out = acc + (bias + va), streaming stores.
#pragma unroll
    for (int mt = 0; mt < 4; mt++) {
        const int r0 = bm * BM + wm * 64 + mt * 16 + (lane >> 2);
#pragma unroll
        for (int nt = 0; nt < 4; nt++) {
            const int col = bn * BN + wn * 32 + nt * 8 + (lane & 3) * 2;
            stg_cs_v2(out + (size_t)r0 * DM + col,
                      acc[mt][nt][0] + addv[nt][0],
                      acc[mt][nt][1] + addv[nt][1]);
            stg_cs_v2(out + (size_t)(r0 + 8) * DM + col,
                      acc[mt][nt][2] + addv[nt][0],
                      acc[mt][nt][3] + addv[nt][1]);
        }
    }
}

// ---------------------------------------------------------------------------
// Launch. Input order: text, acoustic, Wt, bt, Wa, ba, Wq,bq, Wk,bk, Wv,bv
// ---------------------------------------------------------------------------
extern "C" void kernel_launch(void* const* d_in, const int* in_sizes, int n_in,
                              void* d_out, int out_size) {
    const float* text = (const float*)d_in[0];
    const float* ac   = (const float*)d_in[1];
    const float* Wt   = (const float*)d_in[2];
    const float* bt   = (const float*)d_in[3];
    const float* Wa   = (const float*)d_in[4];
    const float* ba   = (const float*)d_in[5];
    const float* Wv   = (const float*)d_in[10];
    const float* bv   = (const float*)d_in[11];
    float* out = (float*)d_out;

    cudaFuncSetAttribute(gemm_kernel,
                         cudaFuncAttributeMaxDynamicSharedMemorySize, SMEM_DYN);

    split_text_kernel<<<(M_TOT * DM) / 8 / 256, 256>>>(text);
    wsplit_kernel<<<dim3(DM / 32, DM / 32), dim3(32, 8)>>>(Wt);
    va_kernel<<<BATCH, DM>>>(ac, Wa, ba, Wv, bv);

    gemm_kernel<<<dim3(DM / BN, M_TOT / BM), 256, SMEM_DYN>>>(bt, out);
}

// round 12
// speedup vs baseline: 1.2622x; 1.0003x over previous
#include <cuda_runtime.h>
#include <cuda_bf16.h>
#include <cstdint>

// ===========================================================================
// CrossModalAttention collapses analytically:
//   fa[b,s,:] constant over s => K_a, V_a constant over t
//   => softmax uniform => attn_out[b,s,:] == va[b,:]
//   => out = text @ Wt + bt + va[b]      (one real GEMM)
// GEMM on tensor cores via bf16x3 fp32 emulation (Ah*Bh + Ah*Bl + Al*Bh).
// Round 10: fix round-9 deadlock. Default cp.async.mbarrier.arrive is
// self-balancing (inc-then-arrive) so the full barrier never flipped.
// Replaced with commit_group / wait_group 1 + explicit mbarrier.arrive from
// the producer warps. Same 128x96 tiles (2048 CTAs, 1.2% wave tail),
// 2 producer + 6 consumer warps, 2 CTAs/SM, no mainloop __syncthreads.
// ===========================================================================

#define BATCH 8
#define SEQ   2048
#define DM    768
#define DAUD  16
#define M_TOT (BATCH * SEQ)

__device__ float g_va[BATCH * DM];
__device__ __nv_bfloat16 g_Ah[M_TOT * DM];
__device__ __nv_bfloat16 g_Al[M_TOT * DM];
__device__ __nv_bfloat16 g_Bh[DM * DM];     // Wt transposed: [N, K]
__device__ __nv_bfloat16 g_Bl[DM * DM];

// ------------------------------ helpers ------------------------------------
__device__ __forceinline__ uint32_t smem_u32(const void* p) {
    uint32_t r;
    asm("{ .reg .u64 t; cvta.to.shared.u64 t, %1; cvt.u32.u64 %0, t; }"
        : "=r"(r) : "l"(p));
    return r;
}

#define SWZ(o) ((o) ^ (((o) >> 3) & 0x70))

__device__ __forceinline__ void cpasync16(uint32_t dst, const void* src) {
    asm volatile("cp.async.cg.shared.global [%0], [%1], 16;"
                 :: "r"(dst), "l"(src));
}

__device__ __forceinline__ void ldsm4(uint32_t* r, uint32_t addr) {
    asm volatile("ldmatrix.sync.aligned.m8n8.x4.shared.b16 {%0,%1,%2,%3}, [%4];"
                 : "=r"(r[0]), "=r"(r[1]), "=r"(r[2]), "=r"(r[3])
                 : "r"(addr));
}

__device__ __forceinline__ void mma16816(float* d,
                                         const uint32_t* a,
                                         uint32_t b0, uint32_t b1) {
    asm volatile(
        "mma.sync.aligned.m16n8k16.row.col.f32.bf16.bf16.f32 "
        "{%0,%1,%2,%3}, {%4,%5,%6,%7}, {%8,%9}, {%0,%1,%2,%3};"
        : "+f"(d[0]), "+f"(d[1]), "+f"(d[2]), "+f"(d[3])
        : "r"(a[0]), "r"(a[1]), "r"(a[2]), "r"(a[3]), "r"(b0), "r"(b1));
}

__device__ __forceinline__ void stg_cs_v2(float* p, float x, float y) {
    asm volatile("st.global.cs.v2.f32 [%0], {%1, %2};"
                 :: "l"(p), "f"(x), "f"(y) : "memory");
}

#define MBARRIER_INIT(addr, cnt) \
    asm volatile("mbarrier.init.shared.b64 [%0], %1;" \
                 :: "r"((uint32_t)(addr)), "r"((uint32_t)(cnt)) : "memory")

#define MBARRIER_ARRIVE(addr) \
    asm volatile("mbarrier.arrive.shared.b64 _, [%0];" \
                 :: "r"((uint32_t)(addr)) : "memory")

#define MBARRIER_WAIT_PARITY(addr, parity) do {                               \
    uint32_t _m = (uint32_t)(addr);                                           \
    uint32_t _p = (uint32_t)(parity);                                         \
    uint32_t _done;                                                           \
    asm volatile(                                                             \
        "{\n\t.reg .pred p;\n\t"                                              \
        "mbarrier.try_wait.parity.acquire.cta.shared::cta.b64 p, [%1], %2;\n\t" \
        "selp.b32 %0, 1, 0, p;\n\t}"                                          \
        : "=r"(_done) : "r"(_m), "r"(_p) : "memory");                         \
    if (!_done) {                                                             \
        asm volatile(                                                         \
            "{\n\t.reg .pred P1;\n\t"                                         \
            "WAIT_LOOP_%=:\n\t"                                               \
            "mbarrier.try_wait.parity.acquire.cta.shared::cta.b64 P1, [%0], %1, 0x989680;\n\t" \
            "@P1 bra.uni WAIT_DONE_%=;\n\t"                                   \
            "bra.uni WAIT_LOOP_%=;\n\t"                                       \
            "WAIT_DONE_%=:\n\t}"                                              \
            :: "r"(_m), "r"(_p) : "memory");                                  \
    }                                                                         \
} while (0)

// ---------------------------------------------------------------------------
// Prep A: fp32 text -> (bf16 hi, bf16 lo), 8 elems/thread, 16B stores.
// ---------------------------------------------------------------------------
__global__ void split_text_kernel(const float* __restrict__ x) {
    size_t i = ((size_t)blockIdx.x * blockDim.x + threadIdx.x) * 8;
    float4 v0 = *(const float4*)(x + i);
    float4 v1 = *(const float4*)(x + i + 4);
    float f[8] = {v0.x, v0.y, v0.z, v0.w, v1.x, v1.y, v1.z, v1.w};
    __nv_bfloat162 h[4], l[4];
#pragma unroll
    for (int j = 0; j < 4; j++) {
        __nv_bfloat16 h0 = __float2bfloat16(f[2*j]);
        __nv_bfloat16 h1 = __float2bfloat16(f[2*j+1]);
        __nv_bfloat16 l0 = __float2bfloat16(f[2*j]   - __bfloat162float(h0));
        __nv_bfloat16 l1 = __float2bfloat16(f[2*j+1] - __bfloat162float(h1));
        h[j] = __halves2bfloat162(h0, h1);
        l[j] = __halves2bfloat162(l0, l1);
    }
    *(uint4*)(g_Ah + i) = *(const uint4*)h;
    *(uint4*)(g_Al + i) = *(const uint4*)l;
}

// ---------------------------------------------------------------------------
// Prep B: transpose + split Wt[K,N] -> g_Bh/g_Bl [N,K]
// ---------------------------------------------------------------------------
__global__ void wsplit_kernel(const float* __restrict__ W) {
    __shared__ float tile[32][33];
    int n0 = blockIdx.x * 32, k0 = blockIdx.y * 32;
    int tx = threadIdx.x, ty = threadIdx.y;
    for (int r = ty; r < 32; r += 8)
        tile[r][tx] = W[(size_t)(k0 + r) * DM + n0 + tx];
    __syncthreads();
    for (int r = ty; r < 32; r += 8) {
        float v = tile[tx][r];                 // = W[k0+tx][n0+r]
        __nv_bfloat16 h = __float2bfloat16(v);
        __nv_bfloat16 l = __float2bfloat16(v - __bfloat162float(h));
        g_Bh[(size_t)(n0 + r) * DM + k0 + tx] = h;
        g_Bl[(size_t)(n0 + r) * DM + k0 + tx] = l;
    }
}

// ---------------------------------------------------------------------------
// Prep C: va[b,:] = (acoustic[b,:] @ Wa + ba) @ Wv + bv
// ---------------------------------------------------------------------------
__global__ void va_kernel(const float* __restrict__ ac,
                          const float* __restrict__ Wa,
                          const float* __restrict__ ba,
                          const float* __restrict__ Wv,
                          const float* __restrict__ bv) {
    __shared__ float fa[DM];
    __shared__ float acs[DAUD];
    const int b = blockIdx.x;
    const int t = threadIdx.x;
    if (t < DAUD) acs[t] = ac[b * DAUD + t];
    __syncthreads();
    float v = ba[t];
#pragma unroll
    for (int k = 0; k < DAUD; k++) v += acs[k] * Wa[k * DM + t];
    fa[t] = v;
    __syncthreads();
    float o = bv[t];
    for (int e = 0; e < DM; e++) o += fa[e] * Wv[e * DM + t];
    g_va[b * DM + t] = o;
}

// ---------------------------------------------------------------------------
// GEMM: CTA tile 128x96, 256 threads. Warps 0-5 consumers (2x3 grid, warp
// tile 64x32), warps 6-7 producers. KT=64, 2-stage mbarrier pipeline.
// Full-signal path: commit_group / wait_group 1 + explicit mbarrier.arrive.
// ---------------------------------------------------------------------------
#define BM      128
#define BN      96
#define KT      64
#define KSTEPS  4
#define NCHUNK  (DM / KT)                 // 12
#define TILE_A  (BM * 128)                // 16 KB
#define TILE_B  (BN * 128)                // 12 KB
#define STAGEB  (2 * TILE_A + 2 * TILE_B) // 56 KB
#define SMEM_DYN (2 * STAGEB)             // 114688 B

__global__ __launch_bounds__(256, 2)
void gemm_kernel(const float* __restrict__ bias, float* __restrict__ out) {
    extern __shared__ __align__(16) char dynsmem[];
    __shared__ __align__(8) uint64_t s_bar[4];   // full[0],full[1],empty[0],empty[1]

    const uint32_t base = smem_u32(dynsmem);
    const int tid = threadIdx.x;
    const int wid = tid >> 5, lane = tid & 31;
    const int bn = blockIdx.x, bm = blockIdx.y;

    const uint32_t full0  = smem_u32(&s_bar[0]);
    const uint32_t empty0 = smem_u32(&s_bar[2]);

    if (tid == 0) {
        MBARRIER_INIT(full0 + 0,  64);    // 64 producer threads arrive
        MBARRIER_INIT(full0 + 8,  64);
        MBARRIER_INIT(empty0 + 0, 192);   // 192 consumer threads arrive
        MBARRIER_INIT(empty0 + 8, 192);
    }
    __syncthreads();

    const __nv_bfloat16* g0[4] = {
        g_Ah + (size_t)bm * BM * DM,
        g_Al + (size_t)bm * BM * DM,
        g_Bh + (size_t)bn * BN * DM,
        g_Bl + (size_t)bn * BN * DM };

    if (wid >= 6) {
        // ------------------------- producer -------------------------------
        const int ptid = tid - 192;             // 0..63
        for (int c = 0; c < NCHUNK; ++c) {
            const int s = c & 1;
            if (c >= 2)
                MBARRIER_WAIT_PARITY(empty0 + 8 * s, ((c >> 1) + 1) & 1);

            const uint32_t stg = base + s * STAGEB;
            const int k0 = c * KT;
            // A hi/lo: 1024 lines of 16B each
#pragma unroll
            for (int t = 0; t < 2; t++) {
                const uint32_t tb = stg + t * TILE_A;
#pragma unroll
                for (int j = 0; j < 16; j++) {
                    const int q = ptid + j * 64;         // 0..1023
                    const int row = q >> 3, cc = q & 7;
                    cpasync16(tb + SWZ(row * 128 + cc * 16),
                              g0[t] + (size_t)row * DM + k0 + cc * 8);
                }
            }
            // B hi/lo: 768 lines each
#pragma unroll
            for (int t = 0; t < 2; t++) {
                const uint32_t tb = stg + 2 * TILE_A + t * TILE_B;
#pragma unroll
                for (int j = 0; j < 12; j++) {
                    const int q = ptid + j * 64;         // 0..767
                    const int row = q >> 3, cc = q & 7;
                    cpasync16(tb + SWZ(row * 128 + cc * 16),
                              g0[2 + t] + (size_t)row * DM + k0 + cc * 8);
                }
            }
            asm volatile("cp.async.commit_group;");
            if (c >= 1) {
                // Chunk c-1's group is now the only one besides the newest.
                asm volatile("cp.async.wait_group 1;");
                MBARRIER_ARRIVE(full0 + 8 * ((c - 1) & 1));
            }
        }
        asm volatile("cp.async.wait_group 0;");
        MBARRIER_ARRIVE(full0 + 8 * ((NCHUNK - 1) & 1));
        return;
    }

    // --------------------------- consumer ---------------------------------
    const int wm = wid / 3;                 // 0..1
    const int wn = wid - wm * 3;            // 0..2

    // Prefetch epilogue addends (bias + va[b]) while pipeline fills.
    const int bidx = bm >> 4;               // (bm*128)/2048
    float addv[4][2];
#pragma unroll
    for (int nt = 0; nt < 4; nt++) {
        const int col = bn * BN + wn * 32 + nt * 8 + (lane & 3) * 2;
        addv[nt][0] = bias[col]     + g_va[bidx * DM + col];
        addv[nt][1] = bias[col + 1] + g_va[bidx * DM + col + 1];
    }

    float acc[4][4][4] = {};

    for (int c = 0; c < NCHUNK; ++c) {
        const int s = c & 1;
        MBARRIER_WAIT_PARITY(full0 + 8 * s, (c >> 1) & 1);

        const uint32_t stg = base + s * STAGEB;
        const uint32_t Ah = stg,               Al = stg + TILE_A;
        const uint32_t Bh = stg + 2 * TILE_A,  Bl = Bh + TILE_B;

#pragma unroll
        for (int ks = 0; ks < KSTEPS; ks++) {
            uint32_t ah[4][4], al[4][4];
            const int akb = ks * 32 + (lane >> 4) * 16;
#pragma unroll
            for (int mt = 0; mt < 4; mt++) {
                const int row = wm * 64 + mt * 16 + (lane & 15);
                const uint32_t off = SWZ(row * 128 + akb);
                ldsm4(ah[mt], Ah + off);
                ldsm4(al[mt], Al + off);
            }
            const int brow_base = wn * 32 + (lane & 7) + ((lane >> 4) << 3);
            const int bkb = ks * 32 + ((lane >> 3) & 1) * 16;
#pragma unroll
            for (int p = 0; p < 2; p++) {
                uint32_t bh[4], bl[4];
                const uint32_t off = SWZ((brow_base + p * 16) * 128 + bkb);
                ldsm4(bh, Bh + off);
                ldsm4(bl, Bl + off);
#pragma unroll
                for (int mt = 0; mt < 4; mt++) {
                    float* d0 = acc[mt][2 * p];
                    float* d1 = acc[mt][2 * p + 1];
                    mma16816(d0, ah[mt], bh[0], bh[1]);
                    mma16816(d1, ah[mt], bh[2], bh[3]);
                    mma16816(d0, ah[mt], bl[0], bl[1]);
                    mma16816(d1, ah[mt], bl[2], bl[3]);
                    mma16816(d0, al[mt], bh[0], bh[1]);
                    mma16816(d1, al[mt], bh[2], bh[3]);
                }
            }
        }
        MBARRIER_ARRIVE(empty0 + 8 * s);
    }

    // Epilogue: out = acc + (bias + va), streaming stores.
#pragma unroll
    for (int mt = 0; mt < 4; mt++) {
        const int r0 = bm * BM + wm * 64 + mt * 16 + (lane >> 2);
#pragma unroll
        for (int nt = 0; nt < 4; nt++) {
            const int col = bn * BN + wn * 32 + nt * 8 + (lane & 3) * 2;
            stg_cs_v2(out + (size_t)r0 * DM + col,
                      acc[mt][nt][0] + addv[nt][0],
                      acc[mt][nt][1] + addv[nt][1]);
            stg_cs_v2(out + (size_t)(r0 + 8) * DM + col,
                      acc[mt][nt][2] + addv[nt][0],
                      acc[mt][nt][3] + addv[nt][1]);
        }
    }
}

// ---------------------------------------------------------------------------
// Launch. Input order: text, acoustic, Wt, bt, Wa, ba, Wq,bq, Wk,bk, Wv,bv
// ---------------------------------------------------------------------------
extern "C" void kernel_launch(void* const* d_in, const int* in_sizes, int n_in,
                              void* d_out, int out_size) {
    const float* text = (const float*)d_in[0];
    const float* ac   = (const float*)d_in[1];
    const float* Wt   = (const float*)d_in[2];
    const float* bt   = (const float*)d_in[3];
    const float* Wa   = (const float*)d_in[4];
    const float* ba   = (const float*)d_in[5];
    const float* Wv   = (const float*)d_in[10];
    const float* bv   = (const float*)d_in[11];
    float* out = (float*)d_out;

    cudaFuncSetAttribute(gemm_kernel,
                         cudaFuncAttributeMaxDynamicSharedMemorySize, SMEM_DYN);

    split_text_kernel<<<(M_TOT * DM) / 8 / 256, 256>>>(text);
    wsplit_kernel<<<dim3(DM / 32, DM / 32), dim3(32, 8)>>>(Wt);
    va_kernel<<<BATCH, DM>>>(ac, Wa, ba, Wv, bv);

    gemm_kernel<<<dim3(DM / BN, M_TOT / BM), 256, SMEM_DYN>>>(bt, out);
}